// round 1
// baseline (speedup 1.0000x reference)
#include <cuda_runtime.h>

// Problem constants
#define SS 7
#define CC 20
#define PSTR 30          // pred floats per cell  (2*5 + 20)
#define TSTR 25          // target floats per cell (20 + 1 + 4)
#define BATCH 8192
#define NCELL (BATCH * SS * SS)      // 401408
#define BLOCK 128
#define NCHUNK (NCELL / BLOCK)       // 3136 (exact)
#define PRED4_PER_CHUNK (BLOCK * PSTR / 4)   // 960
#define TARG4_PER_CHUNK (BLOCK * TSTR / 4)   // 800

// global accumulators: loss, sum(iou*obj), sum(obj)
__device__ float g_acc[3];

__global__ void yolo_init_kernel() {
    g_acc[0] = 0.0f;
    g_acc[1] = 0.0f;
    g_acc[2] = 0.0f;
}

__device__ __forceinline__ float iou_xywh(float ax, float ay, float aw, float ah,
                                          float bx, float by, float bw, float bh) {
    float ax1 = ax - aw * 0.5f, ax2 = ax + aw * 0.5f;
    float ay1 = ay - ah * 0.5f, ay2 = ay + ah * 0.5f;
    float bx1 = bx - bw * 0.5f, bx2 = bx + bw * 0.5f;
    float by1 = by - bh * 0.5f, by2 = by + bh * 0.5f;
    float iw = fmaxf(fminf(ax2, bx2) - fmaxf(ax1, bx1), 0.0f);
    float ih = fmaxf(fminf(ay2, by2) - fmaxf(ay1, by1), 0.0f);
    float inter = iw * ih;
    float uni = fabsf(aw * ah) + fabsf(bw * bh) - inter;
    return inter / (uni + 1e-6f);
}

__global__ __launch_bounds__(BLOCK)
void yolo_main_kernel(const float4* __restrict__ pred4,
                      const float4* __restrict__ targ4) {
    __shared__ float sp[BLOCK * PSTR];   // 15360 B
    __shared__ float st[BLOCK * TSTR];   // 12800 B
    __shared__ float red[3][BLOCK / 32];

    const int tid = threadIdx.x;

    float loss_acc = 0.0f;
    float iou_acc  = 0.0f;
    float cnt_acc  = 0.0f;

    for (int chunk = blockIdx.x; chunk < NCHUNK; chunk += gridDim.x) {
        __syncthreads();  // previous iteration's smem consumers done

        const float4* pc = pred4 + (size_t)chunk * PRED4_PER_CHUNK;
        const float4* tc = targ4 + (size_t)chunk * TARG4_PER_CHUNK;

        float4* sp4 = reinterpret_cast<float4*>(sp);
        float4* st4 = reinterpret_cast<float4*>(st);
        #pragma unroll
        for (int i = tid; i < PRED4_PER_CHUNK; i += BLOCK) sp4[i] = pc[i];
        #pragma unroll
        for (int i = tid; i < TARG4_PER_CHUNK; i += BLOCK) st4[i] = tc[i];
        __syncthreads();

        const float* P = sp + tid * PSTR;
        const float* T = st + tid * TSTR;

        float tconf = T[20];
        float tx = T[21], ty = T[22], tw = T[23], th = T[24];

        float c0 = P[20], x0 = P[21], y0 = P[22], w0 = P[23], h0 = P[24];
        float c1 = P[25], x1 = P[26], y1 = P[27], w1 = P[28], h1 = P[29];

        float i0 = iou_xywh(x0, y0, w0, h0, tx, ty, tw, th);
        float i1 = iou_xywh(x1, y1, w1, h1, tx, ty, tw, th);

        // argmax picks first index on tie -> choose box1 only if strictly greater
        bool sel1 = (i1 > i0);
        float ib  = sel1 ? i1 : i0;
        float pcf = sel1 ? c1 : c0;
        float px  = sel1 ? x1 : x0;
        float py  = sel1 ? y1 : y0;
        float pw  = sel1 ? w1 : w0;
        float ph  = sel1 ? h1 : h0;

        float dx = tx - px, dy = ty - py;
        float center = dx * dx + dy * dy;

        float sw = sqrtf(tw) - sqrtf(fabsf(pw));
        float sh = sqrtf(th) - sqrtf(fabsf(ph));
        float wh = sw * sw + sh * sh;

        float dc = tconf - pcf;
        float confsq = dc * dc;

        float cls = 0.0f;
        #pragma unroll
        for (int k = 0; k < CC; k++) {
            float d = P[k] - T[k];
            cls = fmaf(d, d, cls);
        }

        float obj = (tconf == 1.0f) ? 1.0f : 0.0f;
        loss_acc += obj * (5.0f * (center + wh) + confsq + cls)
                  + (1.0f - obj) * 0.5f * confsq;
        iou_acc  += obj * ib;
        cnt_acc  += obj;
    }

    // warp reduction
    #pragma unroll
    for (int o = 16; o > 0; o >>= 1) {
        loss_acc += __shfl_xor_sync(0xFFFFFFFFu, loss_acc, o);
        iou_acc  += __shfl_xor_sync(0xFFFFFFFFu, iou_acc, o);
        cnt_acc  += __shfl_xor_sync(0xFFFFFFFFu, cnt_acc, o);
    }
    __syncthreads();  // smem (sp/st) no longer needed; reuse barrier for red[]
    int w = tid >> 5, l = tid & 31;
    if (l == 0) {
        red[0][w] = loss_acc;
        red[1][w] = iou_acc;
        red[2][w] = cnt_acc;
    }
    __syncthreads();
    if (tid == 0) {
        float a = 0.0f, b = 0.0f, c = 0.0f;
        #pragma unroll
        for (int i = 0; i < BLOCK / 32; i++) {
            a += red[0][i];
            b += red[1][i];
            c += red[2][i];
        }
        atomicAdd(&g_acc[0], a);
        atomicAdd(&g_acc[1], b);
        atomicAdd(&g_acc[2], c);
    }
}

__global__ void yolo_fin_kernel(float* __restrict__ out, int out_size) {
    out[0] = g_acc[0];
    if (out_size > 1) out[1] = g_acc[1] / fmaxf(g_acc[2], 1.0f);
}

extern "C" void kernel_launch(void* const* d_in, const int* in_sizes, int n_in,
                              void* d_out, int out_size) {
    const float4* pred4 = (const float4*)d_in[0];
    const float4* targ4 = (const float4*)d_in[1];
    float* out = (float*)d_out;

    yolo_init_kernel<<<1, 1>>>();

    int grid = 148 * 8;               // persistent-ish; 3136 chunks / 1184 blocks
    if (grid > NCHUNK) grid = NCHUNK;
    yolo_main_kernel<<<grid, BLOCK>>>(pred4, targ4);

    yolo_fin_kernel<<<1, 1>>>(out, out_size);
}

// round 2
// speedup vs baseline: 1.0152x; 1.0152x over previous
#include <cuda_runtime.h>

// Problem constants
#define SS 7
#define CC 20
#define PSTR 30          // pred floats per cell  (2*5 + 20)
#define TSTR 25          // target floats per cell (20 + 1 + 4)
#define BATCH 8192
#define NCELL (BATCH * SS * SS)      // 401408
#define BLOCK 128
#define NCHUNK (NCELL / BLOCK)       // 3136 (exact)
#define PRED4_PER_CHUNK (BLOCK * PSTR / 4)   // 960
#define TARG4_PER_CHUNK (BLOCK * TSTR / 4)   // 800
#define GRID (148 * 8)               // 1184, one full wave

// global accumulators: loss, sum(iou*obj), sum(obj).
// Zero-initialized at module load; last block resets them each launch,
// so the kernel is deterministic across graph replays.
__device__ float g_acc[3];
__device__ unsigned int g_count;

__device__ __forceinline__ float iou_xywh(float ax, float ay, float aw, float ah,
                                          float bx, float by, float bw, float bh) {
    float ax1 = ax - aw * 0.5f, ax2 = ax + aw * 0.5f;
    float ay1 = ay - ah * 0.5f, ay2 = ay + ah * 0.5f;
    float bx1 = bx - bw * 0.5f, bx2 = bx + bw * 0.5f;
    float by1 = by - bh * 0.5f, by2 = by + bh * 0.5f;
    float iw = fmaxf(fminf(ax2, bx2) - fmaxf(ax1, bx1), 0.0f);
    float ih = fmaxf(fminf(ay2, by2) - fmaxf(ay1, by1), 0.0f);
    float inter = iw * ih;
    float uni = fabsf(aw * ah) + fabsf(bw * bh) - inter;
    return inter / (uni + 1e-6f);
}

__global__ __launch_bounds__(BLOCK)
void yolo_fused_kernel(const float4* __restrict__ pred4,
                       const float4* __restrict__ targ4,
                       float* __restrict__ out, int out_size) {
    __shared__ float sp[BLOCK * PSTR];   // 15360 B
    __shared__ float st[BLOCK * TSTR];   // 12800 B
    __shared__ float red[3][BLOCK / 32];
    __shared__ unsigned int s_last;

    const int tid = threadIdx.x;

    float loss_acc = 0.0f;
    float iou_acc  = 0.0f;
    float cnt_acc  = 0.0f;

    for (int chunk = blockIdx.x; chunk < NCHUNK; chunk += gridDim.x) {
        __syncthreads();  // previous iteration's smem consumers done

        const float4* pc = pred4 + (size_t)chunk * PRED4_PER_CHUNK;
        const float4* tc = targ4 + (size_t)chunk * TARG4_PER_CHUNK;

        float4* sp4 = reinterpret_cast<float4*>(sp);
        float4* st4 = reinterpret_cast<float4*>(st);
        #pragma unroll
        for (int i = tid; i < PRED4_PER_CHUNK; i += BLOCK) sp4[i] = pc[i];
        #pragma unroll
        for (int i = tid; i < TARG4_PER_CHUNK; i += BLOCK) st4[i] = tc[i];
        __syncthreads();

        const float* P = sp + tid * PSTR;
        const float* T = st + tid * TSTR;

        float tconf = T[20];
        float tx = T[21], ty = T[22], tw = T[23], th = T[24];

        float c0 = P[20], x0 = P[21], y0 = P[22], w0 = P[23], h0 = P[24];
        float c1 = P[25], x1 = P[26], y1 = P[27], w1 = P[28], h1 = P[29];

        float i0 = iou_xywh(x0, y0, w0, h0, tx, ty, tw, th);
        float i1 = iou_xywh(x1, y1, w1, h1, tx, ty, tw, th);

        // argmax picks first index on tie -> choose box1 only if strictly greater
        bool sel1 = (i1 > i0);
        float ib  = sel1 ? i1 : i0;
        float pcf = sel1 ? c1 : c0;
        float px  = sel1 ? x1 : x0;
        float py  = sel1 ? y1 : y0;
        float pw  = sel1 ? w1 : w0;
        float ph  = sel1 ? h1 : h0;

        float dx = tx - px, dy = ty - py;
        float center = dx * dx + dy * dy;

        float sw = sqrtf(tw) - sqrtf(fabsf(pw));
        float sh = sqrtf(th) - sqrtf(fabsf(ph));
        float wh = sw * sw + sh * sh;

        float dc = tconf - pcf;
        float confsq = dc * dc;

        float cls = 0.0f;
        #pragma unroll
        for (int k = 0; k < CC; k++) {
            float d = P[k] - T[k];
            cls = fmaf(d, d, cls);
        }

        float obj = (tconf == 1.0f) ? 1.0f : 0.0f;
        loss_acc += obj * (5.0f * (center + wh) + confsq + cls)
                  + (1.0f - obj) * 0.5f * confsq;
        iou_acc  += obj * ib;
        cnt_acc  += obj;
    }

    // warp reduction
    #pragma unroll
    for (int o = 16; o > 0; o >>= 1) {
        loss_acc += __shfl_xor_sync(0xFFFFFFFFu, loss_acc, o);
        iou_acc  += __shfl_xor_sync(0xFFFFFFFFu, iou_acc, o);
        cnt_acc  += __shfl_xor_sync(0xFFFFFFFFu, cnt_acc, o);
    }
    __syncthreads();  // smem (sp/st) no longer needed; reuse barrier for red[]
    int w = tid >> 5, l = tid & 31;
    if (l == 0) {
        red[0][w] = loss_acc;
        red[1][w] = iou_acc;
        red[2][w] = cnt_acc;
    }
    __syncthreads();
    if (tid == 0) {
        float a = 0.0f, b = 0.0f, c = 0.0f;
        #pragma unroll
        for (int i = 0; i < BLOCK / 32; i++) {
            a += red[0][i];
            b += red[1][i];
            c += red[2][i];
        }
        atomicAdd(&g_acc[0], a);
        atomicAdd(&g_acc[1], b);
        atomicAdd(&g_acc[2], c);
        __threadfence();
        unsigned int prev = atomicAdd(&g_count, 1u);
        s_last = (prev == (unsigned int)(gridDim.x - 1)) ? 1u : 0u;
    }
    __syncthreads();

    // Last block finalizes: writes output and resets accumulators so the
    // graph-captured launch is replayable with identical behavior.
    if (s_last && tid == 0) {
        __threadfence();
        // atomic reads guarantee we see the L2-resident accumulator values
        float a = atomicAdd(&g_acc[0], 0.0f);
        float b = atomicAdd(&g_acc[1], 0.0f);
        float c = atomicAdd(&g_acc[2], 0.0f);
        out[0] = a;
        if (out_size > 1) out[1] = b / fmaxf(c, 1.0f);
        g_acc[0] = 0.0f;
        g_acc[1] = 0.0f;
        g_acc[2] = 0.0f;
        g_count  = 0u;
        __threadfence();
    }
}

extern "C" void kernel_launch(void* const* d_in, const int* in_sizes, int n_in,
                              void* d_out, int out_size) {
    const float4* pred4 = (const float4*)d_in[0];
    const float4* targ4 = (const float4*)d_in[1];
    float* out = (float*)d_out;

    yolo_fused_kernel<<<GRID, BLOCK>>>(pred4, targ4, out, out_size);
}

// round 3
// speedup vs baseline: 1.2712x; 1.2521x over previous
#include <cuda_runtime.h>
#include <cstdint>

// Problem constants
#define SS 7
#define CC 20
#define PSTR 30          // pred floats per cell  (2*5 + 20)
#define TSTR 25          // target floats per cell (20 + 1 + 4)
#define BATCH 8192
#define NCELL (BATCH * SS * SS)      // 401408
#define BLOCK 128
#define NCHUNK (NCELL / BLOCK)       // 3136 (exact)
#define PRED4_PER_CHUNK (BLOCK * PSTR / 4)   // 960
#define TARG4_PER_CHUNK (BLOCK * TSTR / 4)   // 800
#define GRID (148 * 4)               // 592 blocks: 4/SM (56.3KB smem each)

// global accumulators: loss, sum(iou*obj), sum(obj).
// Zero at module load; last block resets after finalize -> graph-replayable.
__device__ float g_acc[3];
__device__ unsigned int g_count;

__device__ __forceinline__ void cp_async16(void* smem_dst, const void* gmem_src) {
    uint32_t s = (uint32_t)__cvta_generic_to_shared(smem_dst);
    asm volatile("cp.async.cg.shared.global [%0], [%1], 16;\n" :: "r"(s), "l"(gmem_src));
}
__device__ __forceinline__ void cp_commit() {
    asm volatile("cp.async.commit_group;\n" ::: "memory");
}
template <int N>
__device__ __forceinline__ void cp_wait() {
    asm volatile("cp.async.wait_group %0;\n" :: "n"(N) : "memory");
}

__device__ __forceinline__ float iou_xywh(float ax, float ay, float aw, float ah,
                                          float bx, float by, float bw, float bh) {
    float ax1 = ax - aw * 0.5f, ax2 = ax + aw * 0.5f;
    float ay1 = ay - ah * 0.5f, ay2 = ay + ah * 0.5f;
    float bx1 = bx - bw * 0.5f, bx2 = bx + bw * 0.5f;
    float by1 = by - bh * 0.5f, by2 = by + bh * 0.5f;
    float iw = fmaxf(fminf(ax2, bx2) - fmaxf(ax1, bx1), 0.0f);
    float ih = fmaxf(fminf(ay2, by2) - fmaxf(ay1, by1), 0.0f);
    float inter = iw * ih;
    float uni = fabsf(aw * ah) + fabsf(bw * bh) - inter;
    return inter / (uni + 1e-6f);
}

struct __align__(16) Stage {
    float sp[BLOCK * PSTR];   // 15360 B
    float st[BLOCK * TSTR];   // 12800 B
};

__device__ __forceinline__ void stage_chunk(Stage& buf, int chunk,
                                            const float4* __restrict__ pred4,
                                            const float4* __restrict__ targ4,
                                            int tid) {
    const float4* pc = pred4 + (size_t)chunk * PRED4_PER_CHUNK;
    const float4* tc = targ4 + (size_t)chunk * TARG4_PER_CHUNK;
    float4* sp4 = reinterpret_cast<float4*>(buf.sp);
    float4* st4 = reinterpret_cast<float4*>(buf.st);
    #pragma unroll
    for (int i = tid; i < PRED4_PER_CHUNK; i += BLOCK)
        cp_async16(&sp4[i], &pc[i]);
    #pragma unroll
    for (int i = tid; i < TARG4_PER_CHUNK; i += BLOCK)
        cp_async16(&st4[i], &tc[i]);
    cp_commit();
}

__device__ __forceinline__ void compute_chunk(const Stage& buf, int tid,
                                              float& loss_acc, float& iou_acc,
                                              float& cnt_acc) {
    const float* P = buf.sp + tid * PSTR;
    const float* T = buf.st + tid * TSTR;

    float tconf = T[20];
    float tx = T[21], ty = T[22], tw = T[23], th = T[24];

    float c0 = P[20], x0 = P[21], y0 = P[22], w0 = P[23], h0 = P[24];
    float c1 = P[25], x1 = P[26], y1 = P[27], w1 = P[28], h1 = P[29];

    float i0 = iou_xywh(x0, y0, w0, h0, tx, ty, tw, th);
    float i1 = iou_xywh(x1, y1, w1, h1, tx, ty, tw, th);

    // argmax picks first index on tie -> choose box1 only if strictly greater
    bool sel1 = (i1 > i0);
    float ib  = sel1 ? i1 : i0;
    float pcf = sel1 ? c1 : c0;
    float px  = sel1 ? x1 : x0;
    float py  = sel1 ? y1 : y0;
    float pw  = sel1 ? w1 : w0;
    float ph  = sel1 ? h1 : h0;

    float dx = tx - px, dy = ty - py;
    float center = dx * dx + dy * dy;

    float sw = sqrtf(tw) - sqrtf(fabsf(pw));
    float sh = sqrtf(th) - sqrtf(fabsf(ph));
    float wh = sw * sw + sh * sh;

    float dc = tconf - pcf;
    float confsq = dc * dc;

    float cls = 0.0f;
    #pragma unroll
    for (int k = 0; k < CC; k++) {
        float d = P[k] - T[k];
        cls = fmaf(d, d, cls);
    }

    float obj = (tconf == 1.0f) ? 1.0f : 0.0f;
    loss_acc += obj * (5.0f * (center + wh) + confsq + cls)
              + (1.0f - obj) * 0.5f * confsq;
    iou_acc  += obj * ib;
    cnt_acc  += obj;
}

__global__ __launch_bounds__(BLOCK)
void yolo_fused_kernel(const float4* __restrict__ pred4,
                       const float4* __restrict__ targ4,
                       float* __restrict__ out, int out_size) {
    __shared__ Stage buf[2];             // 56320 B
    __shared__ float red[3][BLOCK / 32];
    __shared__ unsigned int s_last;

    const int tid = threadIdx.x;

    float loss_acc = 0.0f;
    float iou_acc  = 0.0f;
    float cnt_acc  = 0.0f;

    int c = blockIdx.x;
    int cur = 0;
    if (c < NCHUNK)
        stage_chunk(buf[0], c, pred4, targ4, tid);

    while (c < NCHUNK) {
        int next = c + GRID;
        bool has_next = (next < NCHUNK);
        if (has_next) {
            stage_chunk(buf[cur ^ 1], next, pred4, targ4, tid);
            cp_wait<1>();   // oldest group (current buffer) done
        } else {
            cp_wait<0>();
        }
        __syncthreads();    // publish cp.async results to all threads

        compute_chunk(buf[cur], tid, loss_acc, iou_acc, cnt_acc);

        __syncthreads();    // all threads done reading buf[cur] before refill
        cur ^= 1;
        c = next;
    }

    // warp reduction
    #pragma unroll
    for (int o = 16; o > 0; o >>= 1) {
        loss_acc += __shfl_xor_sync(0xFFFFFFFFu, loss_acc, o);
        iou_acc  += __shfl_xor_sync(0xFFFFFFFFu, iou_acc, o);
        cnt_acc  += __shfl_xor_sync(0xFFFFFFFFu, cnt_acc, o);
    }
    int w = tid >> 5, l = tid & 31;
    if (l == 0) {
        red[0][w] = loss_acc;
        red[1][w] = iou_acc;
        red[2][w] = cnt_acc;
    }
    __syncthreads();
    if (tid == 0) {
        float a = 0.0f, b = 0.0f, cc = 0.0f;
        #pragma unroll
        for (int i = 0; i < BLOCK / 32; i++) {
            a  += red[0][i];
            b  += red[1][i];
            cc += red[2][i];
        }
        atomicAdd(&g_acc[0], a);
        atomicAdd(&g_acc[1], b);
        atomicAdd(&g_acc[2], cc);
        __threadfence();
        unsigned int prev = atomicAdd(&g_count, 1u);
        s_last = (prev == (unsigned int)(gridDim.x - 1)) ? 1u : 0u;
    }
    __syncthreads();

    // Last block finalizes and resets accumulators (graph-replay safe).
    if (s_last && tid == 0) {
        __threadfence();
        float a  = atomicAdd(&g_acc[0], 0.0f);
        float b  = atomicAdd(&g_acc[1], 0.0f);
        float cc = atomicAdd(&g_acc[2], 0.0f);
        out[0] = a;
        if (out_size > 1) out[1] = b / fmaxf(cc, 1.0f);
        g_acc[0] = 0.0f;
        g_acc[1] = 0.0f;
        g_acc[2] = 0.0f;
        g_count  = 0u;
        __threadfence();
    }
}

extern "C" void kernel_launch(void* const* d_in, const int* in_sizes, int n_in,
                              void* d_out, int out_size) {
    const float4* pred4 = (const float4*)d_in[0];
    const float4* targ4 = (const float4*)d_in[1];
    float* out = (float*)d_out;

    yolo_fused_kernel<<<GRID, BLOCK>>>(pred4, targ4, out, out_size);
}